// round 11
// baseline (speedup 1.0000x reference)
#include <cuda_runtime.h>
#include <cuda_fp16.h>
#include <cstdint>

#define B_SZ 8
#define NPTS 16384
#define MSRC 1024
#define C1   128
#define C2   256
#define CIN  384
#define CO   256
#define BN_EPS 1e-5f

// ---------------------------------------------------------------------------
// Scratch (allocation-free)
// ---------------------------------------------------------------------------
__device__ __align__(256) float  g_Zt [(size_t)B_SZ * MSRC * CO];
__device__ __align__(256) int4   g_nni[(size_t)B_SZ * NPTS];
__device__ __align__(256) float4 g_nnw[(size_t)B_SZ * NPTS];
__device__ __align__(256) __half g_W0 [CO * C1];
__device__ __align__(256) __half g_W1 [CO * CO];
__device__ __align__(256) __half g_T  [(size_t)B_SZ * NPTS * C1];   // tfeat^T fp16

// ---------------------------------------------------------------------------
// PTX helpers (sm_100-safe)
// ---------------------------------------------------------------------------
__device__ __forceinline__ uint32_t smem_u32(const void* p) {
    uint32_t a;
    asm("{ .reg .u64 t; cvta.to.shared.u64 t, %1; cvt.u32.u64 %0, t; }" : "=r"(a) : "l"(p));
    return a;
}
#define CP16(dst, src) \
    asm volatile("cp.async.cg.shared.global [%0], [%1], 16;" :: "r"(dst), "l"(src))
#define CP_COMMIT() asm volatile("cp.async.commit_group;" ::: "memory")
#define CP_WAIT(n)  asm volatile("cp.async.wait_group %0;" :: "n"(n) : "memory")

#define LDSM4(r, addr) \
    asm volatile("ldmatrix.sync.aligned.m8n8.x4.shared.b16 {%0,%1,%2,%3}, [%4];" \
        : "=r"((r)[0]), "=r"((r)[1]), "=r"((r)[2]), "=r"((r)[3]) : "r"(addr))

#define LDSM4T(r, addr) \
    asm volatile("ldmatrix.sync.aligned.m8n8.x4.trans.shared.b16 {%0,%1,%2,%3}, [%4];" \
        : "=r"((r)[0]), "=r"((r)[1]), "=r"((r)[2]), "=r"((r)[3]) : "r"(addr))

#define MMA_F16(d, a, b0, b1) \
    asm volatile("mma.sync.aligned.m16n8k16.row.col.f32.f16.f16.f32 " \
        "{%0,%1,%2,%3}, {%4,%5,%6,%7}, {%8,%9}, {%0,%1,%2,%3};" \
        : "+f"((d)[0]), "+f"((d)[1]), "+f"((d)[2]), "+f"((d)[3]) \
        : "r"((a)[0]), "r"((a)[1]), "r"((a)[2]), "r"((a)[3]), "r"(b0), "r"(b1))

// ---------------------------------------------------------------------------
// three_nn: 2 target points per thread (halves LDS traffic)
// Grid: (NPTS/512, B), 256 threads.
// ---------------------------------------------------------------------------
__global__ void __launch_bounds__(256)
three_nn_kernel(const float* __restrict__ target, const float* __restrict__ source,
                int4* __restrict__ nni, float4* __restrict__ nnw)
{
    const int b = blockIdx.y, t = threadIdx.x;
    const int ia = blockIdx.x * 512 + t;
    const int ib = ia + 256;
    __shared__ float4 s[MSRC];
    const float* src = source + (size_t)b * MSRC * 3;
    for (int j = t; j < MSRC; j += 256) {
        const float x = src[j * 3 + 0], y = src[j * 3 + 1], z = src[j * 3 + 2];
        s[j] = make_float4(x, y, z, x * x + y * y + z * z);
    }
    __syncthreads();

    const float* tpa = target + ((size_t)b * NPTS + ia) * 3;
    const float* tpb = target + ((size_t)b * NPTS + ib) * 3;
    const float pax = tpa[0], pay = tpa[1], paz = tpa[2];
    const float pbx = tpb[0], pby = tpb[1], pbz = tpb[2];
    const float qax = -2.0f * pax, qay = -2.0f * pay, qaz = -2.0f * paz;
    const float qbx = -2.0f * pbx, qby = -2.0f * pby, qbz = -2.0f * pbz;

    float a0 = 3.4e38f, a1 = 3.4e38f, a2 = 3.4e38f;
    float f0 = 3.4e38f, f1 = 3.4e38f, f2 = 3.4e38f;
    int   ja0 = 0, ja1 = 0, ja2 = 0, jb0 = 0, jb1 = 0, jb2 = 0;
    #pragma unroll 4
    for (int j = 0; j < MSRC; j++) {
        const float4 v = s[j];
        const float ea = fmaf(qax, v.x, fmaf(qay, v.y, fmaf(qaz, v.z, v.w)));
        const float eb = fmaf(qbx, v.x, fmaf(qby, v.y, fmaf(qbz, v.z, v.w)));
        if (ea < a0)      { a2 = a1; ja2 = ja1; a1 = a0; ja1 = ja0; a0 = ea; ja0 = j; }
        else if (ea < a1) { a2 = a1; ja2 = ja1; a1 = ea; ja1 = j; }
        else if (ea < a2) { a2 = ea; ja2 = j; }
        if (eb < f0)      { f2 = f1; jb2 = jb1; f1 = f0; jb1 = jb0; f0 = eb; jb0 = j; }
        else if (eb < f1) { f2 = f1; jb2 = jb1; f1 = eb; jb1 = j; }
        else if (eb < f2) { f2 = eb; jb2 = j; }
    }

    // exact distances + weights for point a
    {
        float d[3]; const int jj[3] = {ja0, ja1, ja2};
        #pragma unroll
        for (int k = 0; k < 3; k++) {
            const float4 v = s[jj[k]];
            const float dx = pax - v.x, dy = pay - v.y, dz = paz - v.z;
            d[k] = dx * dx + dy * dy + dz * dz;
        }
        const float r0 = 1.0f / (d[0] + 1e-8f), r1 = 1.0f / (d[1] + 1e-8f), r2 = 1.0f / (d[2] + 1e-8f);
        const float rs = 1.0f / (r0 + r1 + r2);
        nni[(size_t)b * NPTS + ia] = make_int4(ja0, ja1, ja2, 0);
        nnw[(size_t)b * NPTS + ia] = make_float4(r0 * rs, r1 * rs, r2 * rs, 0.0f);
    }
    // point b
    {
        float d[3]; const int jj[3] = {jb0, jb1, jb2};
        #pragma unroll
        for (int k = 0; k < 3; k++) {
            const float4 v = s[jj[k]];
            const float dx = pbx - v.x, dy = pby - v.y, dz = pbz - v.z;
            d[k] = dx * dx + dy * dy + dz * dz;
        }
        const float r0 = 1.0f / (d[0] + 1e-8f), r1 = 1.0f / (d[1] + 1e-8f), r2 = 1.0f / (d[2] + 1e-8f);
        const float rs = 1.0f / (r0 + r1 + r2);
        nni[(size_t)b * NPTS + ib] = make_int4(jb0, jb1, jb2, 0);
        nnw[(size_t)b * NPTS + ib] = make_float4(r0 * rs, r1 * rs, r2 * rs, 0.0f);
    }
}

// ---------------------------------------------------------------------------
// Zt = (w0[:, :256] @ sfeat)^T per batch (fp32 — keeps interp path exact)
// ---------------------------------------------------------------------------
__global__ void __launch_bounds__(256, 2)
zt_kernel(const float* __restrict__ w0, const float* __restrict__ sfeat, float* __restrict__ Zt)
{
    constexpr int BK = 16, TM = 8, TN = 8;
    __shared__ float Ss[BK][128];
    __shared__ float Ws[BK][128];
    const int b = blockIdx.z, J0 = blockIdx.x * 128, O0 = blockIdx.y * 128;
    const float* sf = sfeat + (size_t)b * C2 * MSRC;
    const int tid = threadIdx.x;
    const int rowO = tid >> 2, colK = (tid & 3) * 4;
    const int rowK = tid >> 5, colJ = (tid & 31) * 4;
    const int tj = (tid >> 4) * TM, to = (tid & 15) * TN;
    float acc[TM][TN];
    #pragma unroll
    for (int i = 0; i < TM; i++)
        #pragma unroll
        for (int j = 0; j < TN; j++) acc[i][j] = 0.0f;
    for (int k0 = 0; k0 < C2; k0 += BK) {
        #pragma unroll
        for (int p = 0; p < 2; p++) {
            const int r = rowO + p * 64;
            const float4 v = *(const float4*)(w0 + (size_t)(O0 + r) * CIN + k0 + colK);
            Ws[colK + 0][r] = v.x; Ws[colK + 1][r] = v.y;
            Ws[colK + 2][r] = v.z; Ws[colK + 3][r] = v.w;
        }
        #pragma unroll
        for (int p = 0; p < 2; p++) {
            const int r = rowK + p * 8;
            *(float4*)&Ss[r][colJ] = *(const float4*)(sf + (size_t)(k0 + r) * MSRC + J0 + colJ);
        }
        __syncthreads();
        #pragma unroll
        for (int kk = 0; kk < BK; kk++) {
            float a[TM], w[TN];
            #pragma unroll
            for (int i = 0; i < TM; i += 4) *(float4*)&a[i] = *(const float4*)&Ss[kk][tj + i];
            #pragma unroll
            for (int j = 0; j < TN; j += 4) *(float4*)&w[j] = *(const float4*)&Ws[kk][to + j];
            #pragma unroll
            for (int i = 0; i < TM; i++)
                #pragma unroll
                for (int j = 0; j < TN; j++) acc[i][j] = fmaf(a[i], w[j], acc[i][j]);
        }
        __syncthreads();
    }
    float* Zb = Zt + (size_t)b * MSRC * CO;
    #pragma unroll
    for (int i = 0; i < TM; i++)
        #pragma unroll
        for (int j = 0; j < TN; j += 4) {
            float4 v = make_float4(acc[i][j], acc[i][j+1], acc[i][j+2], acc[i][j+3]);
            *(float4*)(Zb + (size_t)(J0 + tj + i) * CO + O0 + to + j) = v;
        }
}

// ---------------------------------------------------------------------------
// Weight convert (single fp16 plane)
// ---------------------------------------------------------------------------
__global__ void conv_w_kernel(const float* __restrict__ w, int lda, int c0, int KW,
                              __half* __restrict__ W)
{
    const int idx = blockIdx.x * 256 + threadIdx.x;
    if (idx >= CO * KW) return;
    const int o = idx / KW, k = idx % KW;
    W[idx] = __float2half_rn(w[(size_t)o * lda + c0 + k]);
}

// ---------------------------------------------------------------------------
// tfeat transpose: (B,C1,N) fp32 -> (B,N,C1) fp16
// ---------------------------------------------------------------------------
__global__ void __launch_bounds__(256)
tfeat_t_kernel(const float* __restrict__ tfeat, __half* __restrict__ T)
{
    __shared__ float sm[32][33];
    const int b = blockIdx.z;
    const int n0 = blockIdx.x * 32, c0 = blockIdx.y * 32;
    const int tx = threadIdx.x & 31, ty = threadIdx.x >> 5;
    const float* src = tfeat + (size_t)b * C1 * NPTS;
    #pragma unroll
    for (int i = 0; i < 4; i++) {
        const int c = ty + i * 8;
        sm[c][tx] = src[(size_t)(c0 + c) * NPTS + n0 + tx];
    }
    __syncthreads();
    #pragma unroll
    for (int i = 0; i < 4; i++) {
        const int n = ty + i * 8;
        T[((size_t)b * NPTS + n0 + n) * C1 + c0 + tx] = __float2half_rn(sm[tx][n]);
    }
}

// ---------------------------------------------------------------------------
// Fused 2-layer MLP kernel. One CTA = 128-point tile, 512 threads (16 warps,
// 8m x 2n, warp tile 32m x 64n).
// Stage 1: Y0 = gather(Zt) + BN0(W0 @ T^T) relu  -> smem [o][n] fp16
// Stage 2: out = BN1(W1 @ Y0) relu               -> global fp32 (B,CO,N)
// ---------------------------------------------------------------------------
__global__ void __launch_bounds__(512, 1)
fused_mlp_kernel(const __half* __restrict__ W0, const __half* __restrict__ Tt,
                 const __half* __restrict__ W1, float* __restrict__ out,
                 const float* __restrict__ g0, const float* __restrict__ be0,
                 const float* __restrict__ mu0, const float* __restrict__ var0,
                 const float* __restrict__ g1, const float* __restrict__ be1,
                 const float* __restrict__ mu1, const float* __restrict__ var1,
                 const int4* __restrict__ nni, const float4* __restrict__ nnw,
                 const float* __restrict__ Zt)
{
    constexpr int YROW  = 272;                 // bytes per Y0 row (128 n + 8 pad halves)
    constexpr int YSZ   = 256 * YROW;          // 69632
    constexpr int AOFF0 = YSZ;                 // A stream buf 0 (256 x 144B)
    constexpr int AOFF1 = YSZ + 36864;         // A stream buf 1
    constexpr int BOFF0 = YSZ + 73728;         // B stream buf 0 (128 x 144B)
    constexpr int BOFF1 = YSZ + 92160;         // B stream buf 1
    constexpr int BOUNCE = AOFF1;              // fp32 bounce 128x132 overlaps A1/B0/B1
    extern __shared__ __align__(16) char smem[];
    const uint32_t sb = smem_u32(smem);

    const int tid = threadIdx.x, lane = tid & 31, wid = tid >> 5;
    const int wm = wid >> 1, wn = wid & 1;
    const int bb = blockIdx.y, n0 = blockIdx.x * 128;
    const size_t bnn = (size_t)bb * NPTS;
    const __half* Bg1 = Tt + (bnn + n0) * C1;

    float acc[2][8][4];
    #pragma unroll
    for (int i = 0; i < 2; i++)
        #pragma unroll
        for (int j = 0; j < 8; j++)
            #pragma unroll
            for (int q = 0; q < 4; q++) acc[i][j][q] = 0.0f;

    // ---------------- stage 1: W0 (256x128) @ T^T ----------------
    // prologue: chunk 0
    {
        #pragma unroll
        for (int it = 0; it < 4; it++) {
            const int idx = tid + it * 512, r = idx >> 3, sl = idx & 7;
            CP16(sb + AOFF0 + r * 144 + sl * 16, W0 + (size_t)r * C1 + sl * 8);
        }
        #pragma unroll
        for (int it = 0; it < 2; it++) {
            const int idx = tid + it * 512, r = idx >> 3, sl = idx & 7;
            CP16(sb + BOFF0 + r * 144 + sl * 16, Bg1 + (size_t)r * C1 + sl * 8);
        }
        CP_COMMIT();
    }
    for (int c = 0; c < 2; c++) {
        if (c == 0) {
            #pragma unroll
            for (int it = 0; it < 4; it++) {
                const int idx = tid + it * 512, r = idx >> 3, sl = idx & 7;
                CP16(sb + AOFF1 + r * 144 + sl * 16, W0 + (size_t)r * C1 + 64 + sl * 8);
            }
            #pragma unroll
            for (int it = 0; it < 2; it++) {
                const int idx = tid + it * 512, r = idx >> 3, sl = idx & 7;
                CP16(sb + BOFF1 + r * 144 + sl * 16, Bg1 + (size_t)r * C1 + 64 + sl * 8);
            }
            CP_COMMIT();
            CP_WAIT(1);
        } else {
            CP_WAIT(0);
        }
        __syncthreads();
        const uint32_t ab = sb + (c ? AOFF1 : AOFF0);
        const uint32_t bv = sb + (c ? BOFF1 : BOFF0);
        #pragma unroll
        for (int kk = 0; kk < 4; kk++) {
            uint32_t ah[2][4];
            #pragma unroll
            for (int mt = 0; mt < 2; mt++) {
                const uint32_t ad = ab + (uint32_t)((wm * 32 + mt * 16 + (lane & 15)) * 144
                                                    + (kk * 16 + ((lane >> 4) << 3)) * 2);
                LDSM4(ah[mt], ad);
            }
            #pragma unroll
            for (int ng = 0; ng < 4; ng++) {
                uint32_t bh[4];
                const uint32_t bd = bv + (uint32_t)((wn * 64 + ng * 16 + (lane & 7) + ((lane >> 4) << 3)) * 144
                                                    + (kk * 16 + (((lane >> 3) & 1) << 3)) * 2);
                LDSM4(bh, bd);
                #pragma unroll
                for (int mt = 0; mt < 2; mt++)
                    #pragma unroll
                    for (int hh = 0; hh < 2; hh++)
                        MMA_F16(acc[mt][ng * 2 + hh], ah[mt], bh[2 * hh], bh[2 * hh + 1]);
            }
        }
        __syncthreads();
    }

    // prefetch stage-2 chunk 0 (W1, k0 = 0 -> A0; A0 does not overlap bounce)
    #pragma unroll
    for (int it = 0; it < 4; it++) {
        const int idx = tid + it * 512, r = idx >> 3, sl = idx & 7;
        CP16(sb + AOFF0 + r * 144 + sl * 16, W1 + (size_t)r * CO + sl * 8);
    }
    CP_COMMIT();

    // ---------------- stage-1 epilogue: gather + BN0 + ReLU -> Y0 smem ----------------
    float* S = (float*)(smem + BOUNCE);
    const float* Zb = Zt + (size_t)bb * MSRC * CO;
    #pragma unroll
    for (int h = 0; h < 2; h++) {
        if ((wm >> 2) == h) {
            const int olb = (wm & 3) * 32;
            #pragma unroll
            for (int mt = 0; mt < 2; mt++) {
                const int ol = olb + mt * 16 + (lane >> 2);
                #pragma unroll
                for (int j = 0; j < 8; j++) {
                    const int nl = wn * 64 + j * 8 + (lane & 3) * 2;
                    S[(nl + 0) * 132 + ol]     = acc[mt][j][0];
                    S[(nl + 1) * 132 + ol]     = acc[mt][j][1];
                    S[(nl + 0) * 132 + ol + 8] = acc[mt][j][2];
                    S[(nl + 1) * 132 + ol + 8] = acc[mt][j][3];
                }
            }
        }
        __syncthreads();
        #pragma unroll 1
        for (int it = 0; it < 4; it++) {
            const int item  = tid + it * 512;
            const int o_loc = (item >> 6) << 2;     // 0..124
            const int n2    = (item & 63) << 1;     // 0..126
            const int og    = h * 128 + o_loc;
            float4 v0 = *(float4*)(S + (n2 + 0) * 132 + o_loc);
            float4 v1 = *(float4*)(S + (n2 + 1) * 132 + o_loc);
            {
                const int n = n0 + n2;
                const int4   ji = nni[bnn + n];
                const float4 jw = nnw[bnn + n];
                const float4 z0 = *(const float4*)(Zb + (size_t)ji.x * CO + og);
                const float4 z1 = *(const float4*)(Zb + (size_t)ji.y * CO + og);
                const float4 z2 = *(const float4*)(Zb + (size_t)ji.z * CO + og);
                v0.x += jw.x * z0.x + jw.y * z1.x + jw.z * z2.x;
                v0.y += jw.x * z0.y + jw.y * z1.y + jw.z * z2.y;
                v0.z += jw.x * z0.z + jw.y * z1.z + jw.z * z2.z;
                v0.w += jw.x * z0.w + jw.y * z1.w + jw.z * z2.w;
            }
            {
                const int n = n0 + n2 + 1;
                const int4   ji = nni[bnn + n];
                const float4 jw = nnw[bnn + n];
                const float4 z0 = *(const float4*)(Zb + (size_t)ji.x * CO + og);
                const float4 z1 = *(const float4*)(Zb + (size_t)ji.y * CO + og);
                const float4 z2 = *(const float4*)(Zb + (size_t)ji.z * CO + og);
                v1.x += jw.x * z0.x + jw.y * z1.x + jw.z * z2.x;
                v1.y += jw.x * z0.y + jw.y * z1.y + jw.z * z2.y;
                v1.z += jw.x * z0.z + jw.y * z1.z + jw.z * z2.z;
                v1.w += jw.x * z0.w + jw.y * z1.w + jw.z * z2.w;
            }
            const float4 g4 = *(const float4*)(g0  + og);
            const float4 b4 = *(const float4*)(be0 + og);
            const float4 m4 = *(const float4*)(mu0 + og);
            const float4 q4 = *(const float4*)(var0 + og);
            const float sx = g4.x * rsqrtf(q4.x + BN_EPS), cx = b4.x - m4.x * sx;
            const float sy = g4.y * rsqrtf(q4.y + BN_EPS), cy = b4.y - m4.y * sy;
            const float sz = g4.z * rsqrtf(q4.z + BN_EPS), cz = b4.z - m4.z * sz;
            const float sw = g4.w * rsqrtf(q4.w + BN_EPS), cw = b4.w - m4.w * sw;
            float ya[4], yb[4];
            ya[0] = fmaxf(fmaf(v0.x, sx, cx), 0.0f); yb[0] = fmaxf(fmaf(v1.x, sx, cx), 0.0f);
            ya[1] = fmaxf(fmaf(v0.y, sy, cy), 0.0f); yb[1] = fmaxf(fmaf(v1.y, sy, cy), 0.0f);
            ya[2] = fmaxf(fmaf(v0.z, sz, cz), 0.0f); yb[2] = fmaxf(fmaf(v1.z, sz, cz), 0.0f);
            ya[3] = fmaxf(fmaf(v0.w, sw, cw), 0.0f); yb[3] = fmaxf(fmaf(v1.w, sw, cw), 0.0f);
            #pragma unroll
            for (int r = 0; r < 4; r++) {
                __half2 hv = __halves2half2(__float2half_rn(ya[r]), __float2half_rn(yb[r]));
                *(__half2*)(smem + (og + r) * YROW + n2 * 2) = hv;
            }
        }
        __syncthreads();
    }

    // re-zero accumulators for stage 2
    #pragma unroll
    for (int i = 0; i < 2; i++)
        #pragma unroll
        for (int j = 0; j < 8; j++)
            #pragma unroll
            for (int q = 0; q < 4; q++) acc[i][j][q] = 0.0f;

    // ---------------- stage 2: W1 (256x256) @ Y0 (smem) ----------------
    for (int c = 0; c < 4; c++) {
        if (c < 3) {
            const int k0 = (c + 1) * 64;
            const uint32_t ao = (((c + 1) & 1) ? AOFF1 : AOFF0);
            #pragma unroll
            for (int it = 0; it < 4; it++) {
                const int idx = tid + it * 512, r = idx >> 3, sl = idx & 7;
                CP16(sb + ao + r * 144 + sl * 16, W1 + (size_t)r * CO + k0 + sl * 8);
            }
            CP_COMMIT();
            CP_WAIT(1);
        } else {
            CP_WAIT(0);
        }
        __syncthreads();
        const uint32_t ab = sb + ((c & 1) ? AOFF1 : AOFF0);
        #pragma unroll
        for (int kk = 0; kk < 4; kk++) {
            uint32_t ah[2][4];
            #pragma unroll
            for (int mt = 0; mt < 2; mt++) {
                const uint32_t ad = ab + (uint32_t)((wm * 32 + mt * 16 + (lane & 15)) * 144
                                                    + (kk * 16 + ((lane >> 4) << 3)) * 2);
                LDSM4(ah[mt], ad);
            }
            #pragma unroll
            for (int ng = 0; ng < 4; ng++) {
                uint32_t bh[4];
                const uint32_t bd = sb + (uint32_t)((c * 64 + kk * 16 + (lane & 15)) * YROW
                                                    + (wn * 64 + ng * 16 + ((lane >> 4) << 3)) * 2);
                LDSM4T(bh, bd);
                #pragma unroll
                for (int mt = 0; mt < 2; mt++)
                    #pragma unroll
                    for (int hh = 0; hh < 2; hh++)
                        MMA_F16(acc[mt][ng * 2 + hh], ah[mt], bh[2 * hh], bh[2 * hh + 1]);
            }
        }
        __syncthreads();
    }

    // ---------------- stage-2 epilogue: BN1 + ReLU -> out fp32 ----------------
    #pragma unroll
    for (int mt = 0; mt < 2; mt++) {
        const int o0 = wm * 32 + mt * 16 + (lane >> 2);
        const float s0 = g1[o0] * rsqrtf(var1[o0] + BN_EPS);
        const float c0 = be1[o0] - mu1[o0] * s0;
        const int o1 = o0 + 8;
        const float s1 = g1[o1] * rsqrtf(var1[o1] + BN_EPS);
        const float c1 = be1[o1] - mu1[o1] * s1;
        #pragma unroll
        for (int j = 0; j < 8; j++) {
            const int n = n0 + wn * 64 + j * 8 + (lane & 3) * 2;
            float2 v0, v1;
            v0.x = fmaxf(fmaf(acc[mt][j][0], s0, c0), 0.0f);
            v0.y = fmaxf(fmaf(acc[mt][j][1], s0, c0), 0.0f);
            v1.x = fmaxf(fmaf(acc[mt][j][2], s1, c1), 0.0f);
            v1.y = fmaxf(fmaf(acc[mt][j][3], s1, c1), 0.0f);
            *(float2*)(out + ((size_t)bb * CO + o0) * NPTS + n) = v0;
            *(float2*)(out + ((size_t)bb * CO + o1) * NPTS + n) = v1;
        }
    }
}

// ---------------------------------------------------------------------------
extern "C" void kernel_launch(void* const* d_in, const int* in_sizes, int n_in,
                              void* d_out, int out_size)
{
    const float* target = (const float*)d_in[0];
    const float* source = (const float*)d_in[1];
    const float* tfeat  = (const float*)d_in[2];
    const float* sfeat  = (const float*)d_in[3];
    const float* w0     = (const float*)d_in[4];
    const float* g0     = (const float*)d_in[5];
    const float* b0     = (const float*)d_in[6];
    const float* mu0    = (const float*)d_in[7];
    const float* var0   = (const float*)d_in[8];
    const float* w1     = (const float*)d_in[9];
    const float* g1     = (const float*)d_in[10];
    const float* b1     = (const float*)d_in[11];
    const float* mu1    = (const float*)d_in[12];
    const float* var1   = (const float*)d_in[13];
    float* out = (float*)d_out;

    float*  Zt;  cudaGetSymbolAddress((void**)&Zt,  g_Zt);
    int4*   nni; cudaGetSymbolAddress((void**)&nni, g_nni);
    float4* nnw; cudaGetSymbolAddress((void**)&nnw, g_nnw);
    __half *W0, *W1, *T;
    cudaGetSymbolAddress((void**)&W0, g_W0); cudaGetSymbolAddress((void**)&W1, g_W1);
    cudaGetSymbolAddress((void**)&T,  g_T);

    constexpr int SMEM_FUSED = 256 * 272 + 2 * 36864 + 2 * 18432;  // 180224 B
    cudaFuncSetAttribute(fused_mlp_kernel,
                         cudaFuncAttributeMaxDynamicSharedMemorySize, SMEM_FUSED);

    // 1) three_nn (2 points/thread)
    {
        dim3 grid(NPTS / 512, B_SZ);
        three_nn_kernel<<<grid, 256>>>(target, source, nni, nnw);
    }
    // 2) Zt = (w0[:, :256] @ sfeat)^T  (fp32 — interp path exact)
    {
        dim3 grid(MSRC / 128, CO / 128, B_SZ);
        zt_kernel<<<grid, 256>>>(w0, sfeat, Zt);
    }
    // 3) weight converts
    conv_w_kernel<<<(CO * C1 + 255) / 256, 256>>>(w0, CIN, C2, C1, W0);
    conv_w_kernel<<<(CO * CO + 255) / 256, 256>>>(w1, CO, 0, CO, W1);
    // 4) tfeat transpose -> fp16
    {
        dim3 grid(NPTS / 32, C1 / 32, B_SZ);
        tfeat_t_kernel<<<grid, 256>>>(tfeat, T);
    }
    // 5) fused 2-layer MLP
    {
        dim3 grid(NPTS / 128, B_SZ);
        fused_mlp_kernel<<<grid, 512, SMEM_FUSED>>>(
            W0, T, W1, out,
            g0, b0, mu0, var0, g1, b1, mu1, var1,
            nni, nnw, Zt);
    }
    (void)in_sizes; (void)n_in; (void)out_size;
}

// round 12
// speedup vs baseline: 1.1685x; 1.1685x over previous
#include <cuda_runtime.h>
#include <cuda_fp16.h>
#include <cstdint>

#define B_SZ 8
#define NPTS 16384
#define MSRC 1024
#define C1   128
#define C2   256
#define CIN  384
#define CO   256
#define BN_EPS 1e-5f

// ---------------------------------------------------------------------------
// Scratch (allocation-free)
// ---------------------------------------------------------------------------
__device__ __align__(256) float  g_Zt [(size_t)B_SZ * MSRC * CO];
__device__ __align__(256) int4   g_nni[(size_t)B_SZ * NPTS];
__device__ __align__(256) float4 g_nnw[(size_t)B_SZ * NPTS];
__device__ __align__(256) __half g_W0 [CO * C1];
__device__ __align__(256) __half g_W1 [CO * CO];
__device__ __align__(256) __half g_Y0 [(size_t)B_SZ * NPTS * CO];   // Y0^T fp16

// ---------------------------------------------------------------------------
// PTX helpers (sm_100-safe)
// ---------------------------------------------------------------------------
__device__ __forceinline__ uint32_t smem_u32(const void* p) {
    uint32_t a;
    asm("{ .reg .u64 t; cvta.to.shared.u64 t, %1; cvt.u32.u64 %0, t; }" : "=r"(a) : "l"(p));
    return a;
}
#define CP16(dst, src) \
    asm volatile("cp.async.cg.shared.global [%0], [%1], 16;" :: "r"(dst), "l"(src))
#define CP_COMMIT() asm volatile("cp.async.commit_group;" ::: "memory")
#define CP_WAIT(n)  asm volatile("cp.async.wait_group %0;" :: "n"(n) : "memory")

#define LDSM4(r, addr) \
    asm volatile("ldmatrix.sync.aligned.m8n8.x4.shared.b16 {%0,%1,%2,%3}, [%4];" \
        : "=r"((r)[0]), "=r"((r)[1]), "=r"((r)[2]), "=r"((r)[3]) : "r"(addr))

#define LDSM4T(r, addr) \
    asm volatile("ldmatrix.sync.aligned.m8n8.x4.trans.shared.b16 {%0,%1,%2,%3}, [%4];" \
        : "=r"((r)[0]), "=r"((r)[1]), "=r"((r)[2]), "=r"((r)[3]) : "r"(addr))

#define MMA_F16(d, a, b0, b1) \
    asm volatile("mma.sync.aligned.m16n8k16.row.col.f32.f16.f16.f32 " \
        "{%0,%1,%2,%3}, {%4,%5,%6,%7}, {%8,%9}, {%0,%1,%2,%3};" \
        : "+f"((d)[0]), "+f"((d)[1]), "+f"((d)[2]), "+f"((d)[3]) \
        : "r"((a)[0]), "r"((a)[1]), "r"((a)[2]), "r"((a)[3]), "r"(b0), "r"(b1))

// ---------------------------------------------------------------------------
// three_nn: 2 target points per thread. Grid: (NPTS/512, B), 256 threads.
// ---------------------------------------------------------------------------
__global__ void __launch_bounds__(256)
three_nn_kernel(const float* __restrict__ target, const float* __restrict__ source,
                int4* __restrict__ nni, float4* __restrict__ nnw)
{
    const int b = blockIdx.y, t = threadIdx.x;
    const int ia = blockIdx.x * 512 + t;
    const int ib = ia + 256;
    __shared__ float4 s[MSRC];
    const float* src = source + (size_t)b * MSRC * 3;
    for (int j = t; j < MSRC; j += 256) {
        const float x = src[j * 3 + 0], y = src[j * 3 + 1], z = src[j * 3 + 2];
        s[j] = make_float4(x, y, z, x * x + y * y + z * z);
    }
    __syncthreads();

    const float* tpa = target + ((size_t)b * NPTS + ia) * 3;
    const float* tpb = target + ((size_t)b * NPTS + ib) * 3;
    const float pax = tpa[0], pay = tpa[1], paz = tpa[2];
    const float pbx = tpb[0], pby = tpb[1], pbz = tpb[2];
    const float qax = -2.0f * pax, qay = -2.0f * pay, qaz = -2.0f * paz;
    const float qbx = -2.0f * pbx, qby = -2.0f * pby, qbz = -2.0f * pbz;

    float a0 = 3.4e38f, a1 = 3.4e38f, a2 = 3.4e38f;
    float f0 = 3.4e38f, f1 = 3.4e38f, f2 = 3.4e38f;
    int   ja0 = 0, ja1 = 0, ja2 = 0, jb0 = 0, jb1 = 0, jb2 = 0;
    #pragma unroll 4
    for (int j = 0; j < MSRC; j++) {
        const float4 v = s[j];
        const float ea = fmaf(qax, v.x, fmaf(qay, v.y, fmaf(qaz, v.z, v.w)));
        const float eb = fmaf(qbx, v.x, fmaf(qby, v.y, fmaf(qbz, v.z, v.w)));
        if (ea < a0)      { a2 = a1; ja2 = ja1; a1 = a0; ja1 = ja0; a0 = ea; ja0 = j; }
        else if (ea < a1) { a2 = a1; ja2 = ja1; a1 = ea; ja1 = j; }
        else if (ea < a2) { a2 = ea; ja2 = j; }
        if (eb < f0)      { f2 = f1; jb2 = jb1; f1 = f0; jb1 = jb0; f0 = eb; jb0 = j; }
        else if (eb < f1) { f2 = f1; jb2 = jb1; f1 = eb; jb1 = j; }
        else if (eb < f2) { f2 = eb; jb2 = j; }
    }
    {
        float d[3]; const int jj[3] = {ja0, ja1, ja2};
        #pragma unroll
        for (int k = 0; k < 3; k++) {
            const float4 v = s[jj[k]];
            const float dx = pax - v.x, dy = pay - v.y, dz = paz - v.z;
            d[k] = dx * dx + dy * dy + dz * dz;
        }
        const float r0 = 1.0f / (d[0] + 1e-8f), r1 = 1.0f / (d[1] + 1e-8f), r2 = 1.0f / (d[2] + 1e-8f);
        const float rs = 1.0f / (r0 + r1 + r2);
        nni[(size_t)b * NPTS + ia] = make_int4(ja0, ja1, ja2, 0);
        nnw[(size_t)b * NPTS + ia] = make_float4(r0 * rs, r1 * rs, r2 * rs, 0.0f);
    }
    {
        float d[3]; const int jj[3] = {jb0, jb1, jb2};
        #pragma unroll
        for (int k = 0; k < 3; k++) {
            const float4 v = s[jj[k]];
            const float dx = pbx - v.x, dy = pby - v.y, dz = pbz - v.z;
            d[k] = dx * dx + dy * dy + dz * dz;
        }
        const float r0 = 1.0f / (d[0] + 1e-8f), r1 = 1.0f / (d[1] + 1e-8f), r2 = 1.0f / (d[2] + 1e-8f);
        const float rs = 1.0f / (r0 + r1 + r2);
        nni[(size_t)b * NPTS + ib] = make_int4(jb0, jb1, jb2, 0);
        nnw[(size_t)b * NPTS + ib] = make_float4(r0 * rs, r1 * rs, r2 * rs, 0.0f);
    }
}

// ---------------------------------------------------------------------------
// Zt = (w0[:, :256] @ sfeat)^T per batch (fp32 — keeps interp path exact)
// ---------------------------------------------------------------------------
__global__ void __launch_bounds__(256, 2)
zt_kernel(const float* __restrict__ w0, const float* __restrict__ sfeat, float* __restrict__ Zt)
{
    constexpr int BK = 16, TM = 8, TN = 8;
    __shared__ float Ss[BK][128];
    __shared__ float Ws[BK][128];
    const int b = blockIdx.z, J0 = blockIdx.x * 128, O0 = blockIdx.y * 128;
    const float* sf = sfeat + (size_t)b * C2 * MSRC;
    const int tid = threadIdx.x;
    const int rowO = tid >> 2, colK = (tid & 3) * 4;
    const int rowK = tid >> 5, colJ = (tid & 31) * 4;
    const int tj = (tid >> 4) * TM, to = (tid & 15) * TN;
    float acc[TM][TN];
    #pragma unroll
    for (int i = 0; i < TM; i++)
        #pragma unroll
        for (int j = 0; j < TN; j++) acc[i][j] = 0.0f;
    for (int k0 = 0; k0 < C2; k0 += BK) {
        #pragma unroll
        for (int p = 0; p < 2; p++) {
            const int r = rowO + p * 64;
            const float4 v = *(const float4*)(w0 + (size_t)(O0 + r) * CIN + k0 + colK);
            Ws[colK + 0][r] = v.x; Ws[colK + 1][r] = v.y;
            Ws[colK + 2][r] = v.z; Ws[colK + 3][r] = v.w;
        }
        #pragma unroll
        for (int p = 0; p < 2; p++) {
            const int r = rowK + p * 8;
            *(float4*)&Ss[r][colJ] = *(const float4*)(sf + (size_t)(k0 + r) * MSRC + J0 + colJ);
        }
        __syncthreads();
        #pragma unroll
        for (int kk = 0; kk < BK; kk++) {
            float a[TM], w[TN];
            #pragma unroll
            for (int i = 0; i < TM; i += 4) *(float4*)&a[i] = *(const float4*)&Ss[kk][tj + i];
            #pragma unroll
            for (int j = 0; j < TN; j += 4) *(float4*)&w[j] = *(const float4*)&Ws[kk][to + j];
            #pragma unroll
            for (int i = 0; i < TM; i++)
                #pragma unroll
                for (int j = 0; j < TN; j++) acc[i][j] = fmaf(a[i], w[j], acc[i][j]);
        }
        __syncthreads();
    }
    float* Zb = Zt + (size_t)b * MSRC * CO;
    #pragma unroll
    for (int i = 0; i < TM; i++)
        #pragma unroll
        for (int j = 0; j < TN; j += 4) {
            float4 v = make_float4(acc[i][j], acc[i][j+1], acc[i][j+2], acc[i][j+3]);
            *(float4*)(Zb + (size_t)(J0 + tj + i) * CO + O0 + to + j) = v;
        }
}

// ---------------------------------------------------------------------------
// Weight convert (single fp16 plane)
// ---------------------------------------------------------------------------
__global__ void conv_w_kernel(const float* __restrict__ w, int lda, int c0, int KW,
                              __half* __restrict__ W)
{
    const int idx = blockIdx.x * 256 + threadIdx.x;
    if (idx >= CO * KW) return;
    const int o = idx / KW, k = idx % KW;
    W[idx] = __float2half_rn(w[(size_t)o * lda + c0 + k]);
}

// ---------------------------------------------------------------------------
// Layer 0: W0(128m-tile x K=128) @ tfeat-tile (converted in-kernel) + gather
// + BN + ReLU -> Y0^T fp16.  tfeat consumed DIRECTLY as (B,C1,N) fp32:
// whole 128k x 128n B-tile loaded once, converted to fp16 smem [k][n],
// B fragments via ldmatrix.trans (mapping validated in round 10 stage 2).
// Grid: (NPTS/128, CO/128, B), 256 threads, 2 CTAs/SM.
// ---------------------------------------------------------------------------
__global__ void __launch_bounds__(256, 2)
mma_layer0_kernel(const __half* __restrict__ W0, const float* __restrict__ tfeat,
                  __half* __restrict__ Y0out,
                  const float* __restrict__ gam, const float* __restrict__ bet,
                  const float* __restrict__ mu,  const float* __restrict__ var,
                  const int4* __restrict__ nni, const float4* __restrict__ nnw,
                  const float* __restrict__ Zt)
{
    constexpr int BROW = 272;                  // B smem row stride (bytes)
    constexpr int BS   = 0;                    // B fp16 tile: 128 x 272 = 34816
    constexpr int A0   = 34816;                // A buf 0: 128 x 144 = 18432
    constexpr int A1   = 53248;                // A buf 1
    extern __shared__ __align__(16) char smem[];
    const uint32_t sb = smem_u32(smem);

    const int tid = threadIdx.x, lane = tid & 31, wid = tid >> 5;
    const int wm = wid >> 1, wn = wid & 1;
    const int b = blockIdx.z, n0 = blockIdx.x * 128, m0 = blockIdx.y * 128;
    const size_t bn = (size_t)b * NPTS;

    const __half* A_g = W0 + (size_t)m0 * C1;
    const float*  tf  = tfeat + (size_t)b * C1 * NPTS + n0;

    float acc[2][8][4];
    #pragma unroll
    for (int i = 0; i < 2; i++)
        #pragma unroll
        for (int j = 0; j < 8; j++)
            #pragma unroll
            for (int q = 0; q < 4; q++) acc[i][j][q] = 0.0f;

    // A chunk 0 -> A0
    #pragma unroll
    for (int it = 0; it < 2; it++) {
        const int idx = tid + it * 256, r = idx >> 2, sl = idx & 3;   // 64B payload rows? no:
        (void)r; (void)sl;
    }
    // (A tile rows: 128 x 64 halves = 128B payload; 4 x 16B slots per... use 8 slots of 16B? 64 halves=128B -> 8 slots)
    #pragma unroll
    for (int it = 0; it < 4; it++) {
        const int idx = tid + it * 256;           // 0..1023
        const int r = idx >> 3, sl = idx & 7;     // r 0..127, sl 0..7 (16B each -> 128B)
        CP16(sb + A0 + r * 144 + sl * 16, A_g + (size_t)r * C1 + sl * 8);
    }
    CP_COMMIT();

    // B full tile: 128 k-rows x 128 n, fp32 global -> fp16 smem [k][n]
    {
        const int r  = tid >> 2;            // 0..63
        const int cg = (tid & 3) * 32;      // 0,32,64,96
        #pragma unroll
        for (int half_ = 0; half_ < 2; half_++) {
            const int rr = r + half_ * 64;
            const float* row = tf + (size_t)rr * NPTS + cg;
            #pragma unroll
            for (int i = 0; i < 8; i++) {
                const float4 v = *(const float4*)(row + i * 4);
                __half2 h01 = __floats2half2_rn(v.x, v.y);
                __half2 h23 = __floats2half2_rn(v.z, v.w);
                uint2 pk;
                pk.x = *(uint32_t*)&h01;
                pk.y = *(uint32_t*)&h23;
                *(uint2*)(smem + BS + rr * BROW + (cg + i * 4) * 2) = pk;
            }
        }
    }

    // A chunk 1 -> A1
    #pragma unroll
    for (int it = 0; it < 4; it++) {
        const int idx = tid + it * 256;
        const int r = idx >> 3, sl = idx & 7;
        CP16(sb + A1 + r * 144 + sl * 16, A_g + (size_t)r * C1 + 64 + sl * 8);
    }
    CP_COMMIT();

    CP_WAIT(1);            // A0 done (A1 may still be in flight)
    __syncthreads();       // B tile + A0 visible

    #pragma unroll
    for (int c = 0; c < 2; c++) {
        if (c == 1) { CP_WAIT(0); __syncthreads(); }
        const uint32_t ab = sb + (c ? A1 : A0);
        #pragma unroll
        for (int kk = 0; kk < 4; kk++) {
            uint32_t ah[2][4];
            #pragma unroll
            for (int mt = 0; mt < 2; mt++) {
                const uint32_t ad = ab + (uint32_t)((wm * 32 + mt * 16 + (lane & 15)) * 144
                                                    + (kk * 16 + ((lane >> 4) << 3)) * 2);
                LDSM4(ah[mt], ad);
            }
            #pragma unroll
            for (int ng = 0; ng < 4; ng++) {
                uint32_t bh[4];
                const uint32_t bd = sb + BS
                    + (uint32_t)((c * 64 + kk * 16 + (lane & 15)) * BROW
                                 + (wn * 64 + ng * 16 + ((lane >> 4) << 3)) * 2);
                LDSM4T(bh, bd);
                #pragma unroll
                for (int mt = 0; mt < 2; mt++)
                    #pragma unroll
                    for (int hh = 0; hh < 2; hh++)
                        MMA_F16(acc[mt][ng * 2 + hh], ah[mt], bh[2 * hh], bh[2 * hh + 1]);
            }
        }
    }
    __syncthreads();   // all reads of Bs/A done before bounce overwrites

    // Epilogue: bounce -> gather(Zt) + BN + ReLU -> Y0^T fp16
    float* S = (float*)smem;   // 128 x 132 fp32 = 67584 <= 71680
    #pragma unroll
    for (int mt = 0; mt < 2; mt++) {
        const int ol = wm * 32 + mt * 16 + (lane >> 2);
        #pragma unroll
        for (int j = 0; j < 8; j++) {
            const int nl = wn * 64 + j * 8 + (lane & 3) * 2;
            S[(nl + 0) * 132 + ol]     = acc[mt][j][0];
            S[(nl + 1) * 132 + ol]     = acc[mt][j][1];
            S[(nl + 0) * 132 + ol + 8] = acc[mt][j][2];
            S[(nl + 1) * 132 + ol + 8] = acc[mt][j][3];
        }
    }
    __syncthreads();

    const float* Zb = Zt + (size_t)b * MSRC * CO;
    #pragma unroll 2
    for (int it = 0; it < 16; it++) {
        const int item = tid + it * 256;
        const int nl = item >> 5, o4 = (item & 31) * 4;
        const int n = n0 + nl, o = m0 + o4;
        float4 v = *(float4*)(S + nl * 132 + o4);
        const int4   ji = nni[bn + n];
        const float4 jw = nnw[bn + n];
        const float4 z0 = *(const float4*)(Zb + (size_t)ji.x * CO + o);
        const float4 z1 = *(const float4*)(Zb + (size_t)ji.y * CO + o);
        const float4 z2 = *(const float4*)(Zb + (size_t)ji.z * CO + o);
        v.x += jw.x * z0.x + jw.y * z1.x + jw.z * z2.x;
        v.y += jw.x * z0.y + jw.y * z1.y + jw.z * z2.y;
        v.z += jw.x * z0.z + jw.y * z1.z + jw.z * z2.z;
        v.w += jw.x * z0.w + jw.y * z1.w + jw.z * z2.w;
        const float4 g4 = *(const float4*)(gam + o);
        const float4 b4 = *(const float4*)(bet + o);
        const float4 m4 = *(const float4*)(mu  + o);
        const float4 q4 = *(const float4*)(var + o);
        const float sx = g4.x * rsqrtf(q4.x + BN_EPS);
        const float sy = g4.y * rsqrtf(q4.y + BN_EPS);
        const float sz = g4.z * rsqrtf(q4.z + BN_EPS);
        const float sw = g4.w * rsqrtf(q4.w + BN_EPS);
        union { __half h[4]; uint2 u; } H;
        H.h[0] = __float2half_rn(fmaxf(fmaf(v.x, sx, b4.x - m4.x * sx), 0.0f));
        H.h[1] = __float2half_rn(fmaxf(fmaf(v.y, sy, b4.y - m4.y * sy), 0.0f));
        H.h[2] = __float2half_rn(fmaxf(fmaf(v.z, sz, b4.z - m4.z * sz), 0.0f));
        H.h[3] = __float2half_rn(fmaxf(fmaf(v.w, sw, b4.w - m4.w * sw), 0.0f));
        *(uint2*)(Y0out + (bn + n) * CO + o) = H.u;
    }
}

// ---------------------------------------------------------------------------
// Layer 1: W1 @ Y0^T (both fp16, K-major), cp.async double-buffered, BK=64,
// BN + ReLU -> out fp32 (B, CO, N). Identical to round-8 best.
// ---------------------------------------------------------------------------
__global__ void __launch_bounds__(256, 2)
mma_layer1_kernel(const __half* __restrict__ W, const __half* __restrict__ X,
                  float* __restrict__ outF,
                  const float* __restrict__ gam, const float* __restrict__ bet,
                  const float* __restrict__ mu,  const float* __restrict__ var)
{
    constexpr int KW  = CO;
    constexpr int KC  = KW / 64;
    constexpr int TS  = 128 * 144;
    constexpr int BUF = 2 * TS;
    extern __shared__ __align__(16) char smem[];
    const uint32_t sb = smem_u32(smem);

    const int tid = threadIdx.x, lane = tid & 31, wid = tid >> 5;
    const int wm = wid >> 1, wn = wid & 1;
    const int b = blockIdx.z, n0 = blockIdx.x * 128, m0 = blockIdx.y * 128;

    const __half* A_g = W + (size_t)m0 * KW;
    const __half* B_g = X + ((size_t)b * NPTS + n0) * KW;

    const int lr = tid >> 3;
    const int lc = (tid & 7) * 8;

    float acc[2][8][4];
    #pragma unroll
    for (int i = 0; i < 2; i++)
        #pragma unroll
        for (int j = 0; j < 8; j++)
            #pragma unroll
            for (int q = 0; q < 4; q++) acc[i][j][q] = 0.0f;

    #pragma unroll
    for (int it = 0; it < 4; it++) {
        const int r = lr + it * 32;
        const uint32_t so = (uint32_t)(r * 144 + lc * 2);
        CP16(sb + so,      A_g + (size_t)r * KW + lc);
        CP16(sb + TS + so, B_g + (size_t)r * KW + lc);
    }
    CP_COMMIT();

    for (int c = 0; c < KC; c++) {
        if (c + 1 < KC) {
            const int k0 = (c + 1) * 64;
            const uint32_t bufo = (uint32_t)(((c + 1) & 1) * BUF);
            #pragma unroll
            for (int it = 0; it < 4; it++) {
                const int r = lr + it * 32;
                const uint32_t so = bufo + (uint32_t)(r * 144 + lc * 2);
                CP16(sb + so,      A_g + (size_t)r * KW + k0 + lc);
                CP16(sb + TS + so, B_g + (size_t)r * KW + k0 + lc);
            }
            CP_COMMIT();
            CP_WAIT(1);
        } else {
            CP_WAIT(0);
        }
        __syncthreads();

        const uint32_t base = sb + (uint32_t)((c & 1) * BUF);
        #pragma unroll
        for (int kk = 0; kk < 4; kk++) {
            uint32_t ah[2][4];
            #pragma unroll
            for (int mt = 0; mt < 2; mt++) {
                const uint32_t ad = base
                    + (uint32_t)((wm * 32 + mt * 16 + (lane & 15)) * 144
                                 + (kk * 16 + ((lane >> 4) << 3)) * 2);
                LDSM4(ah[mt], ad);
            }
            #pragma unroll
            for (int ng = 0; ng < 4; ng++) {
                uint32_t bh[4];
                const uint32_t bd = base + TS
                    + (uint32_t)((wn * 64 + ng * 16 + (lane & 7) + ((lane >> 4) << 3)) * 144
                                 + (kk * 16 + (((lane >> 3) & 1) << 3)) * 2);
                LDSM4(bh, bd);
                #pragma unroll
                for (int mt = 0; mt < 2; mt++)
                    #pragma unroll
                    for (int hh = 0; hh < 2; hh++)
                        MMA_F16(acc[mt][ng * 2 + hh], ah[mt], bh[2 * hh], bh[2 * hh + 1]);
            }
        }
        __syncthreads();
    }

    #pragma unroll
    for (int mt = 0; mt < 2; mt++) {
        const int o0 = m0 + wm * 32 + mt * 16 + (lane >> 2);
        const float s0 = gam[o0] * rsqrtf(var[o0] + BN_EPS);
        const float c0 = bet[o0] - mu[o0] * s0;
        const int o1 = o0 + 8;
        const float s1 = gam[o1] * rsqrtf(var[o1] + BN_EPS);
        const float c1 = bet[o1] - mu[o1] * s1;
        #pragma unroll
        for (int j = 0; j < 8; j++) {
            const int n = n0 + wn * 64 + j * 8 + (lane & 3) * 2;
            float2 v0, v1;
            v0.x = fmaxf(fmaf(acc[mt][j][0], s0, c0), 0.0f);
            v0.y = fmaxf(fmaf(acc[mt][j][1], s0, c0), 0.0f);
            v1.x = fmaxf(fmaf(acc[mt][j][2], s1, c1), 0.0f);
            v1.y = fmaxf(fmaf(acc[mt][j][3], s1, c1), 0.0f);
            *(float2*)(outF + ((size_t)b * CO + o0) * NPTS + n) = v0;
            *(float2*)(outF + ((size_t)b * CO + o1) * NPTS + n) = v1;
        }
    }
}

// ---------------------------------------------------------------------------
extern "C" void kernel_launch(void* const* d_in, const int* in_sizes, int n_in,
                              void* d_out, int out_size)
{
    const float* target = (const float*)d_in[0];
    const float* source = (const float*)d_in[1];
    const float* tfeat  = (const float*)d_in[2];
    const float* sfeat  = (const float*)d_in[3];
    const float* w0     = (const float*)d_in[4];
    const float* g0     = (const float*)d_in[5];
    const float* b0     = (const float*)d_in[6];
    const float* mu0    = (const float*)d_in[7];
    const float* var0   = (const float*)d_in[8];
    const float* w1     = (const float*)d_in[9];
    const float* g1     = (const float*)d_in[10];
    const float* b1     = (const float*)d_in[11];
    const float* mu1    = (const float*)d_in[12];
    const float* var1   = (const float*)d_in[13];
    float* out = (float*)d_out;

    float*  Zt;  cudaGetSymbolAddress((void**)&Zt,  g_Zt);
    int4*   nni; cudaGetSymbolAddress((void**)&nni, g_nni);
    float4* nnw; cudaGetSymbolAddress((void**)&nnw, g_nnw);
    __half *W0, *W1, *Y0;
    cudaGetSymbolAddress((void**)&W0, g_W0); cudaGetSymbolAddress((void**)&W1, g_W1);
    cudaGetSymbolAddress((void**)&Y0, g_Y0);

    constexpr int SMEM_L0 = 34816 + 2 * 18432;   // 71680
    constexpr int SMEM_L1 = 2 * 2 * 128 * 144;   // 73728
    cudaFuncSetAttribute(mma_layer0_kernel,
                         cudaFuncAttributeMaxDynamicSharedMemorySize, SMEM_L0);
    cudaFuncSetAttribute(mma_layer1_kernel,
                         cudaFuncAttributeMaxDynamicSharedMemorySize, SMEM_L1);

    // 1) three_nn (2 points/thread)
    {
        dim3 grid(NPTS / 512, B_SZ);
        three_nn_kernel<<<grid, 256>>>(target, source, nni, nnw);
    }
    // 2) Zt = (w0[:, :256] @ sfeat)^T
    {
        dim3 grid(MSRC / 128, CO / 128, B_SZ);
        zt_kernel<<<grid, 256>>>(w0, sfeat, Zt);
    }
    // 3) weight converts
    conv_w_kernel<<<(CO * C1 + 255) / 256, 256>>>(w0, CIN, C2, C1, W0);
    conv_w_kernel<<<(CO * CO + 255) / 256, 256>>>(w1, CO, 0, CO, W1);
    // 4) layer 0 (consumes tfeat directly) -> Y0^T fp16
    {
        dim3 grid(NPTS / 128, CO / 128, B_SZ);
        mma_layer0_kernel<<<grid, 256, SMEM_L0>>>(
            W0, tfeat, Y0, g0, b0, mu0, var0, nni, nnw, Zt);
    }
    // 5) layer 1 -> out fp32
    {
        dim3 grid(NPTS / 128, CO / 128, B_SZ);
        mma_layer1_kernel<<<grid, 256, SMEM_L1>>>(
            W1, Y0, out, g1, b1, mu1, var1);
    }
    (void)in_sizes; (void)n_in; (void)out_size;
}